// round 5
// baseline (speedup 1.0000x reference)
#include <cuda_runtime.h>

// ---------------------------------------------------------------------------
// ContrastiveCRFLoss — B200 (sm_100a), round 5.
//
// Exact-zero sparsity: out[n,a,b] != -0.0 only for pairs with integer
// pixel-dist^2 cd <= 105 (~6k of 1M, batch independent; includes diagonal).
//
// k0 fused_k : wave-interleaved roles (bid-striped, NOT contiguous):
//                bid 0..3            per-row pair enumeration (no atomics)
//                (bid-4) % 4 == 0    gather, 4 plane-loads per thread (MLP=4)
//                else                zero-fill 128 MB output (grid-stride)
// k1 sparse_k: block per row a, warp per pair, lane = batch; A-side record
//              hoisted to registers, all loads coalesced 128B wavefronts.
// ---------------------------------------------------------------------------

#define NB     32
#define KC     27
#define NS     1000
#define HW     256
#define CD_MAX 105.0f
#define ROWCAP 128

#define PAIRB  4                       // pair blocks
#define GATB   1000                    // gather blocks (256k threads, 4 ld/thr)
#define ZFB    3000                    // zfill blocks
#define NBLK   (PAIRB + GATB + ZFB)    // 4004

// record table, transposed: d_recT[s][word][n]; word 0..26 = C, 27..29 = G
__device__ float    d_recT[NS * 32 * NB];        // 4 MB, L2-resident
__device__ unsigned d_rowPair[NS * ROWCAP];      // packed (cd<<10 | b)
__device__ int      d_rowCnt[NS];

// ---------------------------------------------------------------------------
__global__ void __launch_bounds__(256)
fused_k(const float* __restrict__ guidance,
        const float* __restrict__ clusters,
        const int*   __restrict__ coords,
        float4* __restrict__ out, int n4) {
    const int bid = blockIdx.x;
    const int tid = threadIdx.x;

    if (bid < PAIRB) {
        // ---- per-row pair enumeration: thread a scans all b ----
        __shared__ float sr[NS], sc[NS];
        for (int i = tid; i < NS; i += 256) {
            sr[i] = (float)__ldg(&coords[i]);
            sc[i] = (float)__ldg(&coords[NS + i]);
        }
        __syncthreads();

        int a = bid * 256 + tid;
        if (a < NS) {
            float arf = sr[a], acf = sc[a];
            int cnt = 0;
            unsigned* row = d_rowPair + a * ROWCAP;
            #pragma unroll 4
            for (int b = 0; b < NS; b++) {
                float dr = arf - sr[b];
                float dc = acf - sc[b];
                float cd = dr * dr + dc * dc;
                if (cd <= CD_MAX) {
                    if (cnt < ROWCAP)
                        row[cnt] = ((unsigned)(int)cd << 10) | (unsigned)b;
                    cnt++;
                }
            }
            d_rowCnt[a] = cnt < ROWCAP ? cnt : ROWCAP;
        }
        return;
    }

    const int q = bid - PAIRB;
    if ((q & 3) == 0) {
        // ---- gather: thread handles one (s, n, kq); kq<7 -> 4 cluster k's,
        //      kq==7 -> 3 guidance channels.  4 independent loads in flight. ----
        int idx = (q >> 2) * 256 + tid;            // [0, 256000)
        int s    = idx % NS;
        int rest = idx / NS;                       // [0, 256)
        int n  = rest & 31;
        int kq = rest >> 5;                        // [0, 8)

        int r  = __ldg(&coords[s]);
        int c  = __ldg(&coords[NS + s]);
        int px = r * HW + c;

        float* recS = d_recT + (size_t)s * 32 * NB + n;

        if (kq < 7) {
            int k0 = kq * 4;
            float v0, v1, v2, v3;
            const float* base = clusters + (((size_t)n * KC + k0) << 16) + px;
            v0 = __ldg(base);
            v1 = __ldg(base + (1 << 16));
            v2 = __ldg(base + (2 << 16));
            if (k0 + 3 < KC) v3 = __ldg(base + (3 << 16));
            recS[(k0 + 0) * NB] = v0;
            recS[(k0 + 1) * NB] = v1;
            recS[(k0 + 2) * NB] = v2;
            if (k0 + 3 < KC) recS[(k0 + 3) * NB] = v3;
        } else {
            const float* base = guidance + (((size_t)n * 3) << 16) + px;
            float g0 = __ldg(base);
            float g1 = __ldg(base + (1 << 16));
            float g2 = __ldg(base + (2 << 16));
            recS[27 * NB] = g0;
            recS[28 * NB] = g1;
            recS[29 * NB] = g2;
        }
    } else {
        // ---- zero-fill output, grid-stride over ZFB*256 threads ----
        int zid = (q - (q >> 2) - 1) * 256 + tid;  // [0, ZFB*256)
        const int stride = ZFB * 256;
        float4 z = make_float4(0.f, 0.f, 0.f, 0.f);
        for (int i = zid; i < n4; i += stride)
            out[i] = z;
    }
}

// ---------------------------------------------------------------------------
// k1: sparse compute — block per row a, warp per pair slot, lane = batch
// ---------------------------------------------------------------------------
__global__ void __launch_bounds__(256)
sparse_k(float* __restrict__ out) {
    const int a    = blockIdx.x;                 // [0, 1000)
    const int lane = threadIdx.x & 31;           // batch
    const int wid  = threadIdx.x >> 5;           // warp in block

    const int cnt = d_rowCnt[a];

    // hoist A-side record (coalesced: lane sweeps 128B)
    const float* raBase = d_recT + (size_t)a * 32 * NB + lane;
    float ra[30];
    #pragma unroll
    for (int w = 0; w < 30; w++) ra[w] = raBase[w * NB];

    for (int slot = wid; slot < cnt; slot += 8) {
        unsigned e = d_rowPair[a * ROWCAP + slot];
        int   b  = (int)(e & 1023u);
        float cd = (float)(e >> 10);

        const float* rbBase = d_recT + (size_t)b * 32 * NB + lane;

        float dot = 0.f;
        #pragma unroll
        for (int k = 0; k < KC; k++)
            dot = fmaf(ra[k], __ldg(rbBase + k * NB), dot);

        float gd = 0.f;
        #pragma unroll
        for (int ch = 0; ch < 3; ch++) {
            float d = ra[27 + ch] - __ldg(rbBase + (27 + ch) * NB);
            gd = fmaf(d, d, gd);
        }

        float s1 = 10.0f * __expf(-cd - gd * 3.33333333f);
        float s2 = 3.0f  * __expf(-10.0f * cd);

        out[((size_t)lane * NS + a) * NS + b] = -dot * (s1 + s2);
    }
}

// ---------------------------------------------------------------------------
extern "C" void kernel_launch(void* const* d_in, const int* in_sizes, int n_in,
                              void* d_out, int out_size) {
    const float* guidance = (const float*)d_in[0];
    const float* clusters = (const float*)d_in[1];
    const int*   coords   = (const int*)d_in[2];
    float* out = (float*)d_out;

    fused_k<<<NBLK, 256>>>(guidance, clusters, coords,
                           (float4*)out, out_size / 4);
    sparse_k<<<NS, 256>>>(out);
}

// round 6
// speedup vs baseline: 1.1013x; 1.1013x over previous
#include <cuda_runtime.h>

// ---------------------------------------------------------------------------
// ContrastiveCRFLoss — B200 (sm_100a), round 6.
//
// Exact-zero sparsity: out[n,a,b] != ±0.0 only for pairs with integer
// pixel-dist^2 cd <= 105 (~6k of 1M, batch independent).
//
// k0 fused_k (contiguous roles — striping regressed in R5):
//      bid [0,4)        : per-row pair enumeration into d_rowPair/d_rowCnt
//      bid [4,1004)     : gather, ONE SAMPLE PER BLOCK, lane = batch n
//                         -> all recT stores are full 128B coalesced lines,
//                            coord loads warp-uniform
//      bid [1004,4004)  : zero-fill 128MB output, __stcs streaming stores
// k1 sparse_k: one warp per row a, lane = batch; A-record hoisted once,
//              ~6 pairs per row; all recT loads coalesced 128B.
// ---------------------------------------------------------------------------

#define NB     32
#define KC     27
#define NS     1000
#define HW     256
#define CD_MAX 105.0f
#define ROWCAP 64

#define PAIRB  4
#define GATB   1000                     // one block per sample
#define ZFB    3000
#define NBLK   (PAIRB + GATB + ZFB)     // 4004

// record table: d_recT[s][word][n]; word 0..26 = C, 27..29 = G
__device__ float    d_recT[NS * 32 * NB];      // 4 MB
__device__ unsigned d_rowPair[NS * ROWCAP];    // packed (cd<<10 | b)
__device__ int      d_rowCnt[NS];

// ---------------------------------------------------------------------------
__global__ void __launch_bounds__(256)
fused_k(const float* __restrict__ guidance,
        const float* __restrict__ clusters,
        const int*   __restrict__ coords,
        float4* __restrict__ out, int n4) {
    const int bid = blockIdx.x;
    const int tid = threadIdx.x;

    if (bid < PAIRB) {
        // ---- per-row pair enumeration: thread a scans all b ----
        __shared__ float sr[NS], sc[NS];
        for (int i = tid; i < NS; i += 256) {
            sr[i] = (float)__ldg(&coords[i]);
            sc[i] = (float)__ldg(&coords[NS + i]);
        }
        __syncthreads();

        int a = bid * 256 + tid;
        if (a < NS) {
            float arf = sr[a], acf = sc[a];
            int cnt = 0;
            unsigned* row = d_rowPair + a * ROWCAP;
            #pragma unroll 4
            for (int b = 0; b < NS; b++) {
                float dr = arf - sr[b];
                float dc = acf - sc[b];
                float cd = dr * dr + dc * dc;
                if (cd <= CD_MAX && cnt < ROWCAP) {
                    row[cnt] = ((unsigned)(int)cd << 10) | (unsigned)b;
                    cnt++;
                }
            }
            d_rowCnt[a] = cnt;
        }
    } else if (bid < PAIRB + GATB) {
        // ---- gather: block handles sample s; lane = batch n, kq = tid>>5 ----
        const int s  = bid - PAIRB;
        const int n  = tid & 31;
        const int kq = tid >> 5;             // 0..7

        const int r  = __ldg(&coords[s]);    // warp-uniform
        const int c  = __ldg(&coords[NS + s]);
        const int px = r * HW + c;

        float* recS = d_recT + (size_t)s * 32 * NB + n;

        if (kq < 7) {
            const int k0 = kq * 4;           // k0 in {0,4,...,24}; 24+3=27 edge
            const float* base = clusters + (((size_t)n * KC + k0) << 16) + px;
            float v0 = __ldg(base);
            float v1 = __ldg(base + (1 << 16));
            float v2 = __ldg(base + (2 << 16));
            float v3 = (k0 + 3 < KC) ? __ldg(base + (3 << 16)) : 0.f;
            recS[(k0 + 0) * NB] = v0;        // 128B coalesced per warp-store
            recS[(k0 + 1) * NB] = v1;
            recS[(k0 + 2) * NB] = v2;
            if (k0 + 3 < KC) recS[(k0 + 3) * NB] = v3;
        } else {
            const float* base = guidance + (((size_t)n * 3) << 16) + px;
            float g0 = __ldg(base);
            float g1 = __ldg(base + (1 << 16));
            float g2 = __ldg(base + (2 << 16));
            recS[27 * NB] = g0;
            recS[28 * NB] = g1;
            recS[29 * NB] = g2;
        }
    } else {
        // ---- zero-fill output: streaming stores, grid-stride ----
        const int zid = (bid - PAIRB - GATB) * 256 + tid;
        const int stride = ZFB * 256;
        const float4 z = make_float4(0.f, 0.f, 0.f, 0.f);
        for (int i = zid; i < n4; i += stride)
            __stcs(&out[i], z);
    }
}

// ---------------------------------------------------------------------------
// k1: sparse compute — one warp per row a, lane = batch n
// ---------------------------------------------------------------------------
__global__ void __launch_bounds__(256)
sparse_k(float* __restrict__ out) {
    const int gw   = (blockIdx.x * blockDim.x + threadIdx.x) >> 5;  // row a
    const int lane = threadIdx.x & 31;                               // batch n
    if (gw >= NS) return;

    const int a   = gw;
    const int cnt = __ldg(&d_rowCnt[a]);

    // hoist A-side record: 30 coalesced 128B loads
    const float* raBase = d_recT + (size_t)a * 32 * NB + lane;
    float ra[30];
    #pragma unroll
    for (int w = 0; w < 30; w++) ra[w] = __ldg(raBase + w * NB);

    const unsigned* row = d_rowPair + a * ROWCAP;

    for (int slot = 0; slot < cnt; slot++) {
        unsigned e = __ldg(&row[slot]);
        int   b  = (int)(e & 1023u);
        float cd = (float)(e >> 10);

        const float* rbBase = d_recT + (size_t)b * 32 * NB + lane;

        float dot = 0.f;
        #pragma unroll
        for (int k = 0; k < KC; k++)
            dot = fmaf(ra[k], __ldg(rbBase + k * NB), dot);

        float gd = 0.f;
        #pragma unroll
        for (int ch = 0; ch < 3; ch++) {
            float d = ra[27 + ch] - __ldg(rbBase + (27 + ch) * NB);
            gd = fmaf(d, d, gd);
        }

        float s1 = 10.0f * __expf(-cd - gd * 3.33333333f);
        float s2 = 3.0f  * __expf(-10.0f * cd);

        out[((size_t)lane * NS + a) * NS + b] = -dot * (s1 + s2);
    }
}

// ---------------------------------------------------------------------------
extern "C" void kernel_launch(void* const* d_in, const int* in_sizes, int n_in,
                              void* d_out, int out_size) {
    const float* guidance = (const float*)d_in[0];
    const float* clusters = (const float*)d_in[1];
    const int*   coords   = (const int*)d_in[2];
    float* out = (float*)d_out;

    fused_k<<<NBLK, 256>>>(guidance, clusters, coords,
                           (float4*)out, out_size / 4);
    sparse_k<<<(NS * 32 + 255) / 256, 256>>>(out);
}